// round 14
// baseline (speedup 1.0000x reference)
#include <cuda_runtime.h>
#include <cuda_fp16.h>
#include <cstdint>
#include <math.h>

#define T_STEPS 128
#define N_ENV   512
#define IN_D    512
#define HID     512
#define G3      (3 * HID)      // 1536
#define LN_EPS  1e-5f

// ---------------------------------------------------------------------------
// Persistent scratch. g_xf doubles as the h history buffer (x is consumed by
// the GI GEMM before the scan overwrites it with hist[t][env][col]).
// ---------------------------------------------------------------------------
__device__ __half g_gi[(size_t)T_STEPS * N_ENV * G3];         // 201 MB
__device__ __half g_xf[(size_t)T_STEPS * N_ENV * IN_D];       // 67 MB (x, then hist)
__device__ __half g_wih[(size_t)G3 * IN_D];
__device__ __half g_whh[(size_t)G3 * HID];
__device__ __half g_h0[(size_t)N_ENV * HID];                  // initial h (fp16)
__device__ unsigned g_bar8[8];   // per-envgroup barriers

// ---------------------------------------------------------------------------
__global__ void __launch_bounds__(256)
cvt_fp16(const float* __restrict__ src, __half* __restrict__ dst, int n4)
{
    int idx = blockIdx.x * 256 + threadIdx.x;
    if (idx >= n4) return;
    float4 v = ((const float4*)src)[idx];
    ((__half2*)dst)[2 * idx]     = __floats2half2_rn(v.x, v.y);
    ((__half2*)dst)[2 * idx + 1] = __floats2half2_rn(v.z, v.w);
}

// ---------------------------------------------------------------------------
__device__ __forceinline__ void ldsm_x4(uint32_t& r0, uint32_t& r1,
                                        uint32_t& r2, uint32_t& r3,
                                        uint32_t addr)
{
    asm volatile("ldmatrix.sync.aligned.m8n8.x4.shared.b16 {%0,%1,%2,%3}, [%4];\n"
                 : "=r"(r0), "=r"(r1), "=r"(r2), "=r"(r3) : "r"(addr));
}

__device__ __forceinline__ void mma_f32(float* c, const uint32_t* a,
                                        uint32_t b0, uint32_t b1)
{
    asm volatile("mma.sync.aligned.m16n8k16.row.col.f32.f16.f16.f32 "
                 "{%0,%1,%2,%3},{%4,%5,%6,%7},{%8,%9},{%0,%1,%2,%3};\n"
                 : "+f"(c[0]), "+f"(c[1]), "+f"(c[2]), "+f"(c[3])
                 : "r"(a[0]), "r"(a[1]), "r"(a[2]), "r"(a[3]), "r"(b0), "r"(b1));
}

__device__ __forceinline__ float fast_sigmoid(float x)
{
    return __fdividef(1.0f, 1.0f + __expf(-x));
}

__device__ __forceinline__ float fast_tanh(float x)
{
    float t = __expf(2.0f * x);
    return __fdividef(t - 1.0f, t + 1.0f);
}

// ===========================================================================
// GI GEMM: gi_fp16[M,1536] = x_fp16 @ W^T + bias
// CTA tile 128x64 (256 threads, 8 warps 4x2), BK=64.
// ===========================================================================
#define SSTQ 72

__global__ void __launch_bounds__(256)
gemm_gi(const __half* __restrict__ A, const __half* __restrict__ B,
        const float* __restrict__ bias, __half* __restrict__ C, int Nc, int K)
{
    __shared__ __half sA[128 * SSTQ];
    __shared__ __half sB[64 * SSTQ];

    const int tid  = threadIdx.x;
    const int w    = tid >> 5;
    const int lane = tid & 31;
    const int bm   = blockIdx.y * 128;
    const int bn   = blockIdx.x * 64;
    const int wm   = (w & 3) * 32;
    const int wn   = (w >> 2) * 32;

    float acc[2][4][4];
#pragma unroll
    for (int i = 0; i < 2; ++i)
#pragma unroll
        for (int j = 0; j < 4; ++j)
#pragma unroll
            for (int k = 0; k < 4; ++k) acc[i][j][k] = 0.0f;

    const uint32_t sAB = (uint32_t)__cvta_generic_to_shared(sA);
    const uint32_t sBB = (uint32_t)__cvta_generic_to_shared(sB);

    const int a_row = wm + (lane & 7) + ((lane >> 3) & 1) * 8;
    const int a_k   = (lane >> 4) << 3;
    const int b_row = wn + (lane & 7) + ((lane >> 4) << 3);
    const int b_k   = ((lane >> 3) & 1) << 3;

    for (int k0 = 0; k0 < K; k0 += 64) {
#pragma unroll
        for (int i = 0; i < 4; ++i) {
            int idx = tid + i * 256;
            int row = idx >> 3;
            int kc  = (idx & 7) << 3;
            size_t ga = (size_t)(bm + row) * K + k0 + kc;
            int s = row * SSTQ + kc;
            uint4 va = *(const uint4*)(A + ga);
            *(uint2*)&sA[s]     = make_uint2(va.x, va.y);
            *(uint2*)&sA[s + 4] = make_uint2(va.z, va.w);
        }
#pragma unroll
        for (int i = 0; i < 2; ++i) {
            int idx = tid + i * 256;
            int row = idx >> 3;
            int kc  = (idx & 7) << 3;
            size_t gb = (size_t)(bn + row) * K + k0 + kc;
            int s = row * SSTQ + kc;
            uint4 wb = *(const uint4*)(B + gb);
            *(uint2*)&sB[s]     = make_uint2(wb.x, wb.y);
            *(uint2*)&sB[s + 4] = make_uint2(wb.z, wb.w);
        }
        __syncthreads();

#pragma unroll
        for (int kk = 0; kk < 64; kk += 16) {
            const uint32_t mstep = 16 * SSTQ * 2;
            uint32_t aoff = (uint32_t)((a_row * SSTQ + kk + a_k) * 2);
            uint32_t boff = (uint32_t)((b_row * SSTQ + kk + b_k) * 2);

            uint32_t a0[4], a1[4];
            ldsm_x4(a0[0], a0[1], a0[2], a0[3], sAB + aoff);
            ldsm_x4(a1[0], a1[1], a1[2], a1[3], sAB + aoff + mstep);

            uint32_t b0[4], b1[4];
            ldsm_x4(b0[0], b0[1], b0[2], b0[3], sBB + boff);
            ldsm_x4(b1[0], b1[1], b1[2], b1[3], sBB + boff + mstep);

#pragma unroll
            for (int mt = 0; mt < 2; ++mt) {
                const uint32_t* aP = mt ? a1 : a0;
#pragma unroll
                for (int nt = 0; nt < 4; ++nt) {
                    const uint32_t* bP = (nt < 2) ? b0 : b1;
                    int p = (nt & 1) * 2;
                    mma_f32(acc[mt][nt], aP, bP[p], bP[p + 1]);
                }
            }
        }
        __syncthreads();
    }

#pragma unroll
    for (int mt = 0; mt < 2; ++mt) {
#pragma unroll
        for (int nt = 0; nt < 4; ++nt) {
            int r0 = bm + wm + mt * 16 + (lane >> 2);
            int cg = bn + wn + nt * 8 + ((lane & 3) << 1);
            float b0 = bias[cg], b1 = bias[cg + 1];
            *(__half2*)(C + (size_t)r0 * Nc + cg) =
                __floats2half2_rn(acc[mt][nt][0] + b0, acc[mt][nt][1] + b1);
            *(__half2*)(C + (size_t)(r0 + 8) * Nc + cg) =
                __floats2half2_rn(acc[mt][nt][2] + b0, acc[mt][nt][3] + b1);
        }
    }
}

// ===========================================================================
// Persistent fused GRU scan. Grid (16, 8) = 128 CTAs x 256 threads.
// Double-buffered 128-K h chunks (staging overlaps mma); release/acquire
// inter-CTA barrier (no full membar). h stored once, fp16, into hist[t].
// ===========================================================================
#define WSTR  520
#define HSTR2 136
#define SM_W  0
#define SM_H0 (96 * WSTR)                 // 49920
#define SM_H1 (96 * WSTR + 64 * HSTR2)    // 58624
#define SMEM_ELEMS (96 * WSTR + 2 * 64 * HSTR2)   // 67328 halves = 131.5 KB

__global__ void __launch_bounds__(256)
gru_scan(const __half* __restrict__ gi_all, const float* __restrict__ masks,
         const __half* __restrict__ h0init, const float* __restrict__ b_hh,
         float* __restrict__ out, __half* __restrict__ hist)
{
    extern __shared__ __half sm[];
    __half* sW = sm + SM_W;

    const int tid  = threadIdx.x;
    const int w    = tid >> 5;
    const int lane = tid & 31;
    const int wq   = w >> 1;
    const int wr   = w & 1;
    const int c0   = blockIdx.x * 32;
    const int gy   = blockIdx.y;
    const int bm   = gy * 64;

    const uint32_t sWB  = (uint32_t)__cvta_generic_to_shared(sW);
    const uint32_t sH0B = (uint32_t)__cvta_generic_to_shared(sm + SM_H0);
    const uint32_t sH1B = (uint32_t)__cvta_generic_to_shared(sm + SM_H1);

    // ---- stage W_hh slice once: 96 rows x 512 K ----
    for (int i = tid; i < 96 * 64; i += 256) {
        int row = i >> 6;
        int seg = (i & 63) << 3;
        int ch  = row >> 5;
        int c   = row & 31;
        size_t g = (size_t)(ch * HID + c0 + c) * HID + seg;
        *(uint4*)&sW[row * WSTR + seg] = *(const uint4*)&g_whh[g];
    }

    const int env0 = bm + wq * 16 + (lane >> 2);
    const int env1 = env0 + 8;
    const int colbase = c0 + wr * 16;

    float bh[3][2][2], hprev[2][2][2];
#pragma unroll
    for (int ch = 0; ch < 3; ++ch)
#pragma unroll
        for (int nt = 0; nt < 2; ++nt) {
            int col = colbase + nt * 8 + ((lane & 3) << 1);
            bh[ch][nt][0] = b_hh[ch * HID + col];
            bh[ch][nt][1] = b_hh[ch * HID + col + 1];
        }
#pragma unroll
    for (int e = 0; e < 2; ++e)
#pragma unroll
        for (int nt = 0; nt < 2; ++nt) {
            int env = e ? env1 : env0;
            int col = colbase + nt * 8 + ((lane & 3) << 1);
            float2 v = __half22float2(*(const __half2*)&h0init[(size_t)env * HID + col]);
            hprev[e][nt][0] = v.x; hprev[e][nt][1] = v.y;
        }

    const int a_row = wq * 16 + (lane & 7) + (((lane >> 3) & 1) << 3);
    const int a_k   = (lane >> 4) << 3;
    const int b_rowL = wr * 16 + (lane & 7) + ((lane >> 4) << 3);
    const int b_k   = ((lane >> 3) & 1) << 3;

    // staging coords: row = tid>>2 (0..63), seg = (tid&3)*32 within 128-K chunk
    const int st_row = tid >> 2;
    const int st_seg = (tid & 3) << 5;

    unsigned long long barp = (unsigned long long)&g_bar8[gy];

    __syncthreads();

    for (int t = 0; t < T_STEPS; ++t) {
        const __half* Rd = (t == 0) ? h0init
                                    : (hist + (size_t)(t - 1) * N_ENV * HID);
        __half* Hw = hist + (size_t)t * N_ENV * HID;
        const float* mrow = masks + (size_t)t * N_ENV;

        float m_e0 = mrow[env0];
        float m_e1 = mrow[env1];
        float m_st = mrow[bm + st_row];

        // ---- prefetch gate inputs (fp16, DRAM) early ----
        float grv[2][2][2], gzv[2][2][2], gnv[2][2][2];
        {
            const __half* gip = gi_all + (size_t)t * N_ENV * G3;
#pragma unroll
            for (int e = 0; e < 2; ++e) {
                int env = e ? env1 : env0;
#pragma unroll
                for (int nt = 0; nt < 2; ++nt) {
                    int col = colbase + nt * 8 + ((lane & 3) << 1);
                    size_t gb = (size_t)env * G3 + col;
                    float2 a = __half22float2(*(const __half2*)&gip[gb]);
                    float2 b = __half22float2(*(const __half2*)&gip[gb + HID]);
                    float2 c = __half22float2(*(const __half2*)&gip[gb + 2 * HID]);
                    grv[e][nt][0] = a.x; grv[e][nt][1] = a.y;
                    gzv[e][nt][0] = b.x; gzv[e][nt][1] = b.y;
                    gnv[e][nt][0] = c.x; gnv[e][nt][1] = c.y;
                }
            }
        }

        float acc[3][2][4];
#pragma unroll
        for (int ch = 0; ch < 3; ++ch)
#pragma unroll
            for (int nt = 0; nt < 2; ++nt)
#pragma unroll
                for (int j = 0; j < 4; ++j) acc[ch][nt][j] = 0.0f;

        // preload chunk 0 (128 K) into registers
        uint4 pv[4], nv[4];
        {
            size_t g = (size_t)(bm + st_row) * HID + st_seg;
#pragma unroll
            for (int j = 0; j < 4; ++j) pv[j] = *(const uint4*)&Rd[g + j * 8];
        }

        for (int cnk = 0; cnk < 4; ++cnk) {
            // store current chunk into buffer (cnk&1); mask-zero dead rows
            {
                __half* sH = sm + ((cnk & 1) ? SM_H1 : SM_H0);
                uint4 z = make_uint4(0, 0, 0, 0);
                int s = st_row * HSTR2 + st_seg;
#pragma unroll
                for (int j = 0; j < 4; ++j)
                    *(uint4*)&sH[s + j * 8] = (m_st == 0.0f) ? z : pv[j];
            }
            // issue next chunk's global loads (overlap with this chunk's mma)
            if (cnk < 3) {
                size_t g = (size_t)(bm + st_row) * HID + (cnk + 1) * 128 + st_seg;
#pragma unroll
                for (int j = 0; j < 4; ++j) nv[j] = *(const uint4*)&Rd[g + j * 8];
            }
            __syncthreads();

            const uint32_t sHB = (cnk & 1) ? sH1B : sH0B;
            const int k0 = cnk * 128;
#pragma unroll
            for (int kk = 0; kk < 128; kk += 16) {
                uint32_t aoff = (uint32_t)((a_row * HSTR2 + kk + a_k) * 2);
                uint32_t ah[4];
                ldsm_x4(ah[0], ah[1], ah[2], ah[3], sHB + aoff);

#pragma unroll
                for (int ch = 0; ch < 3; ++ch) {
                    uint32_t boff = (uint32_t)(((ch * 32 + b_rowL) * WSTR
                                               + k0 + kk + b_k) * 2);
                    uint32_t bk[4];
                    ldsm_x4(bk[0], bk[1], bk[2], bk[3], sWB + boff);
#pragma unroll
                    for (int nt = 0; nt < 2; ++nt) {
                        int p = nt * 2;
                        mma_f32(acc[ch][nt], ah, bk[p], bk[p + 1]);
                    }
                }
            }
#pragma unroll
            for (int j = 0; j < 4; ++j) pv[j] = nv[j];
        }

        // ---- fused gate; single fp16 hist store per element ----
#pragma unroll
        for (int e = 0; e < 2; ++e) {
            int env = e ? env1 : env0;
            float m = e ? m_e1 : m_e0;
#pragma unroll
            for (int nt = 0; nt < 2; ++nt) {
                int col = colbase + nt * 8 + ((lane & 3) << 1);
                int j0 = 2 * e;

                float hr0 = acc[0][nt][j0]     + bh[0][nt][0];
                float hr1 = acc[0][nt][j0 + 1] + bh[0][nt][1];
                float hz0 = acc[1][nt][j0]     + bh[1][nt][0];
                float hz1 = acc[1][nt][j0 + 1] + bh[1][nt][1];
                float hn0 = acc[2][nt][j0]     + bh[2][nt][0];
                float hn1 = acc[2][nt][j0 + 1] + bh[2][nt][1];

                float r0 = fast_sigmoid(grv[e][nt][0] + hr0);
                float r1 = fast_sigmoid(grv[e][nt][1] + hr1);
                float z0 = fast_sigmoid(gzv[e][nt][0] + hz0);
                float z1 = fast_sigmoid(gzv[e][nt][1] + hz1);
                float n0 = fast_tanh(gnv[e][nt][0] + r0 * hn0);
                float n1 = fast_tanh(gnv[e][nt][1] + r1 * hn1);

                float h0v = hprev[e][nt][0] * m;
                float h1v = hprev[e][nt][1] * m;
                float hw0 = (1.0f - z0) * n0 + z0 * h0v;
                float hw1 = (1.0f - z1) * n1 + z1 * h1v;
                hprev[e][nt][0] = hw0;
                hprev[e][nt][1] = hw1;

                *(__half2*)&Hw[(size_t)env * HID + col]
                    = __floats2half2_rn(hw0, hw1);
                if (t == T_STEPS - 1) {
                    *(float2*)&out[(size_t)T_STEPS * N_ENV * HID
                                   + (size_t)env * HID + col]
                        = make_float2(hw0, hw1);
                }
            }
        }

        // ---- per-envgroup barrier: release/acquire, no full membar ----
        if (t < T_STEPS - 1) {
            __syncthreads();   // all CTA stores ordered before tid0's release
            if (tid == 0) {
                unsigned target = 16u * (unsigned)(t + 1);
                unsigned old;
                asm volatile("atom.release.gpu.global.add.u32 %0, [%1], %2;"
                             : "=r"(old) : "l"(barp), "r"(1u) : "memory");
                unsigned v;
                do {
                    asm volatile("ld.acquire.gpu.global.u32 %0, [%1];"
                                 : "=r"(v) : "l"(barp) : "memory");
                } while (v < target);
            }
            __syncthreads();   // acquire visible to whole CTA
        }
    }
}

// ---------------------------------------------------------------------------
// LayerNorm: reads fp16 hist rows, writes fp32 normed rows into d_out.
// ---------------------------------------------------------------------------
__global__ void __launch_bounds__(128)
layernorm_rows(const __half* __restrict__ hist, float* __restrict__ out,
               const float* __restrict__ w, const float* __restrict__ b)
{
    __shared__ float ss[4], sqs[4];
    const __half* p = hist + (size_t)blockIdx.x * HID;
    float* q = out + (size_t)blockIdx.x * HID;
    int t = threadIdx.x;

    float2 v01 = __half22float2(((const __half2*)p)[2 * t]);
    float2 v23 = __half22float2(((const __half2*)p)[2 * t + 1]);
    float4 v = make_float4(v01.x, v01.y, v23.x, v23.y);

    float s  = v.x + v.y + v.z + v.w;
    float sq = v.x * v.x + v.y * v.y + v.z * v.z + v.w * v.w;

#pragma unroll
    for (int o = 16; o > 0; o >>= 1) {
        s  += __shfl_xor_sync(0xffffffffu, s,  o);
        sq += __shfl_xor_sync(0xffffffffu, sq, o);
    }
    int warp = t >> 5;
    if ((t & 31) == 0) { ss[warp] = s; sqs[warp] = sq; }
    __syncthreads();
    s  = ss[0]  + ss[1]  + ss[2]  + ss[3];
    sq = sqs[0] + sqs[1] + sqs[2] + sqs[3];

    float mu  = s * (1.0f / HID);
    float var = sq * (1.0f / HID) - mu * mu;
    float inv = rsqrtf(var + LN_EPS);

    float4 wv = ((const float4*)w)[t];
    float4 bv = ((const float4*)b)[t];
    float4 o;
    o.x = (v.x - mu) * inv * wv.x + bv.x;
    o.y = (v.y - mu) * inv * wv.y + bv.y;
    o.z = (v.z - mu) * inv * wv.z + bv.z;
    o.w = (v.w - mu) * inv * wv.w + bv.w;
    ((float4*)q)[t] = o;
}

// ---------------------------------------------------------------------------
extern "C" void kernel_launch(void* const* d_in, const int* in_sizes, int n_in,
                              void* d_out, int out_size)
{
    const float* x     = (const float*)d_in[0];
    const float* hxs   = (const float*)d_in[1];
    const float* masks = (const float*)d_in[2];
    const float* W_ih  = (const float*)d_in[3];
    const float* W_hh  = (const float*)d_in[4];
    const float* b_ih  = (const float*)d_in[5];
    const float* b_hh  = (const float*)d_in[6];
    const float* ln_w  = (const float*)d_in[7];
    const float* ln_b  = (const float*)d_in[8];
    float* out = (float*)d_out;

    __half *gi, *xf, *wih, *whh, *h0;
    unsigned* barp;
    cudaGetSymbolAddress((void**)&gi, g_gi);
    cudaGetSymbolAddress((void**)&xf, g_xf);
    cudaGetSymbolAddress((void**)&wih, g_wih);
    cudaGetSymbolAddress((void**)&whh, g_whh);
    cudaGetSymbolAddress((void**)&h0, g_h0);
    cudaGetSymbolAddress((void**)&barp, g_bar8);

    cudaMemsetAsync(barp, 0, 8 * sizeof(unsigned));

    // 0) One-time fp32 -> fp16 conversions.
    {
        int n4;
        n4 = T_STEPS * N_ENV * IN_D / 4;
        cvt_fp16<<<(n4 + 255) / 256, 256>>>(x, xf, n4);
        n4 = G3 * IN_D / 4;
        cvt_fp16<<<(n4 + 255) / 256, 256>>>(W_ih, wih, n4);
        n4 = G3 * HID / 4;
        cvt_fp16<<<(n4 + 255) / 256, 256>>>(W_hh, whh, n4);
        n4 = N_ENV * HID / 4;
        cvt_fp16<<<(n4 + 255) / 256, 256>>>(hxs, h0, n4);
    }

    // 1) GI = x @ W_ih^T + b_ih (fp16 out). Consumes xf completely.
    {
        dim3 grid(G3 / 64, (T_STEPS * N_ENV) / 128);
        gemm_gi<<<grid, 256>>>(xf, wih, b_ih, gi, G3, IN_D);
    }

    // 2) Persistent fused scan; hist into xf (now dead) + h_last tail.
    {
        size_t smem = (size_t)SMEM_ELEMS * sizeof(__half);
        cudaFuncSetAttribute(gru_scan, cudaFuncAttributeMaxDynamicSharedMemorySize,
                             (int)smem);
        dim3 grid(HID / 32, N_ENV / 64);   // 16 x 8 = 128 CTAs
        gru_scan<<<grid, 256, smem>>>(gi, masks, h0, b_hh, out, xf);
    }

    // 3) LayerNorm: fp16 hist -> fp32 normed out.
    layernorm_rows<<<T_STEPS * N_ENV, 128>>>(xf, out, ln_w, ln_b);
}

// round 15
// speedup vs baseline: 1.4695x; 1.4695x over previous
#include <cuda_runtime.h>
#include <cuda_fp16.h>
#include <cstdint>
#include <math.h>

#define T_STEPS 128
#define N_ENV   512
#define IN_D    512
#define HID     512
#define G3      (3 * HID)      // 1536
#define LN_EPS  1e-5f

// ---------------------------------------------------------------------------
// Persistent scratch. g_xf doubles as the h history buffer (x is consumed by
// the GI GEMM before the scan overwrites it with hist[t][env][col]).
// ---------------------------------------------------------------------------
__device__ __half g_gi[(size_t)T_STEPS * N_ENV * G3];         // 201 MB
__device__ __half g_xf[(size_t)T_STEPS * N_ENV * IN_D];       // 67 MB (x, then hist)
__device__ __half g_wih[(size_t)G3 * IN_D];
__device__ __half g_whh[(size_t)G3 * HID];
__device__ __half g_h0[(size_t)N_ENV * HID];                  // initial h (fp16)
__device__ unsigned g_bar8[8];   // per-envgroup barriers

// ---------------------------------------------------------------------------
// Merged fp32 -> fp16 conversion over 4 concatenated ranges (1 launch).
// ---------------------------------------------------------------------------
#define CVT_N0 (T_STEPS * N_ENV * IN_D / 4)   // x
#define CVT_N1 (G3 * IN_D / 4)                // W_ih
#define CVT_N2 (G3 * HID / 4)                 // W_hh
#define CVT_N3 (N_ENV * HID / 4)              // hxs
#define CVT_TOT (CVT_N0 + CVT_N1 + CVT_N2 + CVT_N3)

__global__ void __launch_bounds__(256)
cvt_all(const float* __restrict__ s0, __half* __restrict__ d0,
        const float* __restrict__ s1, __half* __restrict__ d1,
        const float* __restrict__ s2, __half* __restrict__ d2,
        const float* __restrict__ s3, __half* __restrict__ d3)
{
    int idx = blockIdx.x * 256 + threadIdx.x;
    if (idx >= CVT_TOT) return;
    const float* src; __half* dst; int off;
    if (idx < CVT_N0)                         { src = s0; dst = d0; off = idx; }
    else if (idx < CVT_N0 + CVT_N1)           { src = s1; dst = d1; off = idx - CVT_N0; }
    else if (idx < CVT_N0 + CVT_N1 + CVT_N2)  { src = s2; dst = d2; off = idx - CVT_N0 - CVT_N1; }
    else                                      { src = s3; dst = d3; off = idx - CVT_N0 - CVT_N1 - CVT_N2; }
    float4 v = ((const float4*)src)[off];
    ((__half2*)dst)[2 * off]     = __floats2half2_rn(v.x, v.y);
    ((__half2*)dst)[2 * off + 1] = __floats2half2_rn(v.z, v.w);
}

// ---------------------------------------------------------------------------
__device__ __forceinline__ void ldsm_x4(uint32_t& r0, uint32_t& r1,
                                        uint32_t& r2, uint32_t& r3,
                                        uint32_t addr)
{
    asm volatile("ldmatrix.sync.aligned.m8n8.x4.shared.b16 {%0,%1,%2,%3}, [%4];\n"
                 : "=r"(r0), "=r"(r1), "=r"(r2), "=r"(r3) : "r"(addr));
}

__device__ __forceinline__ void mma_f32(float* c, const uint32_t* a,
                                        uint32_t b0, uint32_t b1)
{
    asm volatile("mma.sync.aligned.m16n8k16.row.col.f32.f16.f16.f32 "
                 "{%0,%1,%2,%3},{%4,%5,%6,%7},{%8,%9},{%0,%1,%2,%3};\n"
                 : "+f"(c[0]), "+f"(c[1]), "+f"(c[2]), "+f"(c[3])
                 : "r"(a[0]), "r"(a[1]), "r"(a[2]), "r"(a[3]), "r"(b0), "r"(b1));
}

__device__ __forceinline__ float fast_sigmoid(float x)
{
    return __fdividef(1.0f, 1.0f + __expf(-x));
}

__device__ __forceinline__ float fast_tanh(float x)
{
    float t = __expf(2.0f * x);
    return __fdividef(t - 1.0f, t + 1.0f);
}

// ===========================================================================
// GI GEMM: gi_fp16[M,1536] = x_fp16 @ W^T + bias
// CTA tile 128x64 (256 threads, 8 warps 4x2), BK=64.
// ===========================================================================
#define SSTQ 72

__global__ void __launch_bounds__(256)
gemm_gi(const __half* __restrict__ A, const __half* __restrict__ B,
        const float* __restrict__ bias, __half* __restrict__ C, int Nc, int K)
{
    __shared__ __half sA[128 * SSTQ];
    __shared__ __half sB[64 * SSTQ];

    const int tid  = threadIdx.x;
    const int w    = tid >> 5;
    const int lane = tid & 31;
    const int bm   = blockIdx.y * 128;
    const int bn   = blockIdx.x * 64;
    const int wm   = (w & 3) * 32;
    const int wn   = (w >> 2) * 32;

    float acc[2][4][4];
#pragma unroll
    for (int i = 0; i < 2; ++i)
#pragma unroll
        for (int j = 0; j < 4; ++j)
#pragma unroll
            for (int k = 0; k < 4; ++k) acc[i][j][k] = 0.0f;

    const uint32_t sAB = (uint32_t)__cvta_generic_to_shared(sA);
    const uint32_t sBB = (uint32_t)__cvta_generic_to_shared(sB);

    const int a_row = wm + (lane & 7) + ((lane >> 3) & 1) * 8;
    const int a_k   = (lane >> 4) << 3;
    const int b_row = wn + (lane & 7) + ((lane >> 4) << 3);
    const int b_k   = ((lane >> 3) & 1) << 3;

    for (int k0 = 0; k0 < K; k0 += 64) {
#pragma unroll
        for (int i = 0; i < 4; ++i) {
            int idx = tid + i * 256;
            int row = idx >> 3;
            int kc  = (idx & 7) << 3;
            size_t ga = (size_t)(bm + row) * K + k0 + kc;
            int s = row * SSTQ + kc;
            uint4 va = *(const uint4*)(A + ga);
            *(uint2*)&sA[s]     = make_uint2(va.x, va.y);
            *(uint2*)&sA[s + 4] = make_uint2(va.z, va.w);
        }
#pragma unroll
        for (int i = 0; i < 2; ++i) {
            int idx = tid + i * 256;
            int row = idx >> 3;
            int kc  = (idx & 7) << 3;
            size_t gb = (size_t)(bn + row) * K + k0 + kc;
            int s = row * SSTQ + kc;
            uint4 wb = *(const uint4*)(B + gb);
            *(uint2*)&sB[s]     = make_uint2(wb.x, wb.y);
            *(uint2*)&sB[s + 4] = make_uint2(wb.z, wb.w);
        }
        __syncthreads();

#pragma unroll
        for (int kk = 0; kk < 64; kk += 16) {
            const uint32_t mstep = 16 * SSTQ * 2;
            uint32_t aoff = (uint32_t)((a_row * SSTQ + kk + a_k) * 2);
            uint32_t boff = (uint32_t)((b_row * SSTQ + kk + b_k) * 2);

            uint32_t a0[4], a1[4];
            ldsm_x4(a0[0], a0[1], a0[2], a0[3], sAB + aoff);
            ldsm_x4(a1[0], a1[1], a1[2], a1[3], sAB + aoff + mstep);

            uint32_t b0[4], b1[4];
            ldsm_x4(b0[0], b0[1], b0[2], b0[3], sBB + boff);
            ldsm_x4(b1[0], b1[1], b1[2], b1[3], sBB + boff + mstep);

#pragma unroll
            for (int mt = 0; mt < 2; ++mt) {
                const uint32_t* aP = mt ? a1 : a0;
#pragma unroll
                for (int nt = 0; nt < 4; ++nt) {
                    const uint32_t* bP = (nt < 2) ? b0 : b1;
                    int p = (nt & 1) * 2;
                    mma_f32(acc[mt][nt], aP, bP[p], bP[p + 1]);
                }
            }
        }
        __syncthreads();
    }

#pragma unroll
    for (int mt = 0; mt < 2; ++mt) {
#pragma unroll
        for (int nt = 0; nt < 4; ++nt) {
            int r0 = bm + wm + mt * 16 + (lane >> 2);
            int cg = bn + wn + nt * 8 + ((lane & 3) << 1);
            float b0 = bias[cg], b1 = bias[cg + 1];
            *(__half2*)(C + (size_t)r0 * Nc + cg) =
                __floats2half2_rn(acc[mt][nt][0] + b0, acc[mt][nt][1] + b1);
            *(__half2*)(C + (size_t)(r0 + 8) * Nc + cg) =
                __floats2half2_rn(acc[mt][nt][2] + b0, acc[mt][nt][3] + b1);
        }
    }
}

// ===========================================================================
// Persistent fused GRU scan. Grid (16, 8) = 128 CTAs x 256 threads.
// R13 structure: single full-K h buffer, 2 syncs/step. Release/acquire
// inter-CTA barrier (no MEMBAR.GPU). h stored once, fp16, into hist[t].
// ===========================================================================
#define WSTR 520
#define HSTR 520
#define SM_W  0
#define SM_H  (96 * WSTR)
#define SMEM_ELEMS (96 * WSTR + 64 * HSTR)   // 162.5 KB

__global__ void __launch_bounds__(256)
gru_scan(const __half* __restrict__ gi_all, const float* __restrict__ masks,
         const __half* __restrict__ h0init, const float* __restrict__ b_hh,
         float* __restrict__ out, __half* __restrict__ hist)
{
    extern __shared__ __half sm[];
    __half* sW = sm + SM_W;
    __half* sH = sm + SM_H;

    const int tid  = threadIdx.x;
    const int w    = tid >> 5;
    const int lane = tid & 31;
    const int wq   = w >> 1;
    const int wr   = w & 1;
    const int c0   = blockIdx.x * 32;
    const int gy   = blockIdx.y;
    const int bm   = gy * 64;

    const uint32_t sWB = (uint32_t)__cvta_generic_to_shared(sW);
    const uint32_t sHB = (uint32_t)__cvta_generic_to_shared(sH);

    // ---- stage W_hh slice once: 96 rows x 512 K ----
    for (int i = tid; i < 96 * 64; i += 256) {
        int row = i >> 6;
        int seg = (i & 63) << 3;
        int ch  = row >> 5;
        int c   = row & 31;
        size_t g = (size_t)(ch * HID + c0 + c) * HID + seg;
        *(uint4*)&sW[row * WSTR + seg] = *(const uint4*)&g_whh[g];
    }

    const int env0 = bm + wq * 16 + (lane >> 2);
    const int env1 = env0 + 8;
    const int colbase = c0 + wr * 16;

    float bh[3][2][2], hprev[2][2][2];
#pragma unroll
    for (int ch = 0; ch < 3; ++ch)
#pragma unroll
        for (int nt = 0; nt < 2; ++nt) {
            int col = colbase + nt * 8 + ((lane & 3) << 1);
            bh[ch][nt][0] = b_hh[ch * HID + col];
            bh[ch][nt][1] = b_hh[ch * HID + col + 1];
        }
#pragma unroll
    for (int e = 0; e < 2; ++e)
#pragma unroll
        for (int nt = 0; nt < 2; ++nt) {
            int env = e ? env1 : env0;
            int col = colbase + nt * 8 + ((lane & 3) << 1);
            float2 v = __half22float2(*(const __half2*)&h0init[(size_t)env * HID + col]);
            hprev[e][nt][0] = v.x; hprev[e][nt][1] = v.y;
        }

    const int a_row = wq * 16 + (lane & 7) + (((lane >> 3) & 1) << 3);
    const int a_k   = (lane >> 4) << 3;
    const int b_rowL = wr * 16 + (lane & 7) + ((lane >> 4) << 3);
    const int b_k   = ((lane >> 3) & 1) << 3;

    unsigned long long barp = (unsigned long long)&g_bar8[gy];

    __syncthreads();

    for (int t = 0; t < T_STEPS; ++t) {
        const __half* Rd = (t == 0) ? h0init
                                    : (hist + (size_t)(t - 1) * N_ENV * HID);
        __half* Hw = hist + (size_t)t * N_ENV * HID;
        const float* mrow = masks + (size_t)t * N_ENV;

        float m_e0 = mrow[env0];
        float m_e1 = mrow[env1];

        // ---- prefetch gate inputs (fp16, DRAM) early ----
        float grv[2][2][2], gzv[2][2][2], gnv[2][2][2];
        {
            const __half* gip = gi_all + (size_t)t * N_ENV * G3;
#pragma unroll
            for (int e = 0; e < 2; ++e) {
                int env = e ? env1 : env0;
#pragma unroll
                for (int nt = 0; nt < 2; ++nt) {
                    int col = colbase + nt * 8 + ((lane & 3) << 1);
                    size_t gb = (size_t)env * G3 + col;
                    float2 a = __half22float2(*(const __half2*)&gip[gb]);
                    float2 b = __half22float2(*(const __half2*)&gip[gb + HID]);
                    float2 c = __half22float2(*(const __half2*)&gip[gb + 2 * HID]);
                    grv[e][nt][0] = a.x; grv[e][nt][1] = a.y;
                    gzv[e][nt][0] = b.x; gzv[e][nt][1] = b.y;
                    gnv[e][nt][0] = c.x; gnv[e][nt][1] = c.y;
                }
            }
        }

        // ---- stage full h tile (64 envs x 512 K), mask-zero dead rows ----
#pragma unroll 4
        for (int i = tid; i < 64 * 64; i += 256) {
            int row = i >> 6;
            int seg = (i & 63) << 3;
            float m = mrow[bm + row];
            uint4 v = *(const uint4*)&Rd[(size_t)(bm + row) * HID + seg];
            if (m == 0.0f) v = make_uint4(0, 0, 0, 0);
            *(uint4*)&sH[row * HSTR + seg] = v;
        }
        __syncthreads();

        float acc[3][2][4];
#pragma unroll
        for (int ch = 0; ch < 3; ++ch)
#pragma unroll
            for (int nt = 0; nt < 2; ++nt)
#pragma unroll
                for (int j = 0; j < 4; ++j) acc[ch][nt][j] = 0.0f;

#pragma unroll 8
        for (int kk = 0; kk < 512; kk += 16) {
            uint32_t aoff = (uint32_t)((a_row * HSTR + kk + a_k) * 2);
            uint32_t ah[4];
            ldsm_x4(ah[0], ah[1], ah[2], ah[3], sHB + aoff);

#pragma unroll
            for (int ch = 0; ch < 3; ++ch) {
                uint32_t boff = (uint32_t)(((ch * 32 + b_rowL) * WSTR
                                           + kk + b_k) * 2);
                uint32_t bk[4];
                ldsm_x4(bk[0], bk[1], bk[2], bk[3], sWB + boff);
#pragma unroll
                for (int nt = 0; nt < 2; ++nt) {
                    int p = nt * 2;
                    mma_f32(acc[ch][nt], ah, bk[p], bk[p + 1]);
                }
            }
        }

        // ---- fused gate; single fp16 hist store per element ----
#pragma unroll
        for (int e = 0; e < 2; ++e) {
            int env = e ? env1 : env0;
            float m = e ? m_e1 : m_e0;
#pragma unroll
            for (int nt = 0; nt < 2; ++nt) {
                int col = colbase + nt * 8 + ((lane & 3) << 1);
                int j0 = 2 * e;

                float hr0 = acc[0][nt][j0]     + bh[0][nt][0];
                float hr1 = acc[0][nt][j0 + 1] + bh[0][nt][1];
                float hz0 = acc[1][nt][j0]     + bh[1][nt][0];
                float hz1 = acc[1][nt][j0 + 1] + bh[1][nt][1];
                float hn0 = acc[2][nt][j0]     + bh[2][nt][0];
                float hn1 = acc[2][nt][j0 + 1] + bh[2][nt][1];

                float r0 = fast_sigmoid(grv[e][nt][0] + hr0);
                float r1 = fast_sigmoid(grv[e][nt][1] + hr1);
                float z0 = fast_sigmoid(gzv[e][nt][0] + hz0);
                float z1 = fast_sigmoid(gzv[e][nt][1] + hz1);
                float n0 = fast_tanh(gnv[e][nt][0] + r0 * hn0);
                float n1 = fast_tanh(gnv[e][nt][1] + r1 * hn1);

                float h0v = hprev[e][nt][0] * m;
                float h1v = hprev[e][nt][1] * m;
                float hw0 = (1.0f - z0) * n0 + z0 * h0v;
                float hw1 = (1.0f - z1) * n1 + z1 * h1v;
                hprev[e][nt][0] = hw0;
                hprev[e][nt][1] = hw1;

                *(__half2*)&Hw[(size_t)env * HID + col]
                    = __floats2half2_rn(hw0, hw1);
                if (t == T_STEPS - 1) {
                    *(float2*)&out[(size_t)T_STEPS * N_ENV * HID
                                   + (size_t)env * HID + col]
                        = make_float2(hw0, hw1);
                }
            }
        }

        // ---- per-envgroup barrier: release/acquire (no MEMBAR.GPU) ----
        if (t < T_STEPS - 1) {
            __syncthreads();   // orders all CTA stores before tid0's release
            if (tid == 0) {
                unsigned target = 16u * (unsigned)(t + 1);
                unsigned old;
                asm volatile("atom.release.gpu.global.add.u32 %0, [%1], %2;"
                             : "=r"(old) : "l"(barp), "r"(1u) : "memory");
                unsigned v;
                do {
                    asm volatile("ld.acquire.gpu.global.u32 %0, [%1];"
                                 : "=r"(v) : "l"(barp) : "memory");
                } while (v < target);
            }
            __syncthreads();   // acquire result visible CTA-wide
        }
    }
}

// ---------------------------------------------------------------------------
// LayerNorm: reads fp16 hist rows, writes fp32 normed rows into d_out.
// ---------------------------------------------------------------------------
__global__ void __launch_bounds__(128)
layernorm_rows(const __half* __restrict__ hist, float* __restrict__ out,
               const float* __restrict__ w, const float* __restrict__ b)
{
    __shared__ float ss[4], sqs[4];
    const __half* p = hist + (size_t)blockIdx.x * HID;
    float* q = out + (size_t)blockIdx.x * HID;
    int t = threadIdx.x;

    float2 v01 = __half22float2(((const __half2*)p)[2 * t]);
    float2 v23 = __half22float2(((const __half2*)p)[2 * t + 1]);
    float4 v = make_float4(v01.x, v01.y, v23.x, v23.y);

    float s  = v.x + v.y + v.z + v.w;
    float sq = v.x * v.x + v.y * v.y + v.z * v.z + v.w * v.w;

#pragma unroll
    for (int o = 16; o > 0; o >>= 1) {
        s  += __shfl_xor_sync(0xffffffffu, s,  o);
        sq += __shfl_xor_sync(0xffffffffu, sq, o);
    }
    int warp = t >> 5;
    if ((t & 31) == 0) { ss[warp] = s; sqs[warp] = sq; }
    __syncthreads();
    s  = ss[0]  + ss[1]  + ss[2]  + ss[3];
    sq = sqs[0] + sqs[1] + sqs[2] + sqs[3];

    float mu  = s * (1.0f / HID);
    float var = sq * (1.0f / HID) - mu * mu;
    float inv = rsqrtf(var + LN_EPS);

    float4 wv = ((const float4*)w)[t];
    float4 bv = ((const float4*)b)[t];
    float4 o;
    o.x = (v.x - mu) * inv * wv.x + bv.x;
    o.y = (v.y - mu) * inv * wv.y + bv.y;
    o.z = (v.z - mu) * inv * wv.z + bv.z;
    o.w = (v.w - mu) * inv * wv.w + bv.w;
    ((float4*)q)[t] = o;
}

// ---------------------------------------------------------------------------
extern "C" void kernel_launch(void* const* d_in, const int* in_sizes, int n_in,
                              void* d_out, int out_size)
{
    const float* x     = (const float*)d_in[0];
    const float* hxs   = (const float*)d_in[1];
    const float* masks = (const float*)d_in[2];
    const float* W_ih  = (const float*)d_in[3];
    const float* W_hh  = (const float*)d_in[4];
    const float* b_ih  = (const float*)d_in[5];
    const float* b_hh  = (const float*)d_in[6];
    const float* ln_w  = (const float*)d_in[7];
    const float* ln_b  = (const float*)d_in[8];
    float* out = (float*)d_out;

    __half *gi, *xf, *wih, *whh, *h0;
    unsigned* barp;
    cudaGetSymbolAddress((void**)&gi, g_gi);
    cudaGetSymbolAddress((void**)&xf, g_xf);
    cudaGetSymbolAddress((void**)&wih, g_wih);
    cudaGetSymbolAddress((void**)&whh, g_whh);
    cudaGetSymbolAddress((void**)&h0, g_h0);
    cudaGetSymbolAddress((void**)&barp, g_bar8);

    cudaMemsetAsync(barp, 0, 8 * sizeof(unsigned));

    // 0) One-time fp32 -> fp16 conversions (single merged launch).
    cvt_all<<<(CVT_TOT + 255) / 256, 256>>>(x, xf, W_ih, wih, W_hh, whh, hxs, h0);

    // 1) GI = x @ W_ih^T + b_ih (fp16 out). Consumes xf completely.
    {
        dim3 grid(G3 / 64, (T_STEPS * N_ENV) / 128);
        gemm_gi<<<grid, 256>>>(xf, wih, b_ih, gi, G3, IN_D);
    }

    // 2) Persistent fused scan; hist into xf (now dead) + h_last tail.
    {
        size_t smem = (size_t)SMEM_ELEMS * sizeof(__half);
        cudaFuncSetAttribute(gru_scan, cudaFuncAttributeMaxDynamicSharedMemorySize,
                             (int)smem);
        dim3 grid(HID / 32, N_ENV / 64);   // 16 x 8 = 128 CTAs
        gru_scan<<<grid, 256, smem>>>(gi, masks, h0, b_hh, out, xf);
    }

    // 3) LayerNorm: fp16 hist -> fp32 normed out.
    layernorm_rows<<<T_STEPS * N_ENV, 128>>>(xf, out, ln_w, ln_b);
}